// round 12
// baseline (speedup 1.0000x reference)
#include <cuda_runtime.h>
#include <math.h>
#include <cstdint>

#define B_CONST 2
#define H_NUM   16
#define HD      32

// ---------------- device scratch ----------------
__device__ float g_q [2*2048*512];
__device__ float g_k [2*2048*512];
__device__ float g_v [2*2048*512];
__device__ float g_ao[2*2048*512];
__device__ int g_gcols[64];
__device__ int g_gcount;

// ---------------- global-token column list ----------------
__global__ void glist_kernel(int S, const int* __restrict__ Gptr) {
    if (threadIdx.x != 0 || blockIdx.x != 0) return;
    int G = *Gptr;
    int n = 0;
    if (G > 0) {
        int stride = S / (G + 1);
        if (G == 1) {
            g_gcols[n++] = stride;
        } else {
            double stp = (double)(S - 2 * stride) / (double)(G - 1);
            for (int t = 0; t < G && n < 64; t++) {
                long long gi = (t == G - 1)
                    ? (long long)(S - stride)
                    : (long long)((double)t * stp + (double)stride);
                bool dup = false;
                for (int u = 0; u < n; u++) if (g_gcols[u] == (int)gi) dup = true;
                if (!dup) g_gcols[n++] = (int)gi;
            }
        }
    }
    g_gcount = n;
}

// ---------------- shared helpers ----------------
__device__ __forceinline__ uint32_t f2tf32(float x) {
    uint32_t r;
    asm("cvt.rna.tf32.f32 %0, %1;" : "=r"(r) : "f"(x));
    return r;
}

__device__ __forceinline__ void mma_tf32(float* c, const uint32_t* a, const uint32_t* b) {
    asm volatile(
        "mma.sync.aligned.m16n8k8.row.col.f32.tf32.tf32.f32 "
        "{%0,%1,%2,%3}, {%4,%5,%6,%7}, {%8,%9}, {%0,%1,%2,%3};"
        : "+f"(c[0]), "+f"(c[1]), "+f"(c[2]), "+f"(c[3])
        : "r"(a[0]), "r"(a[1]), "r"(a[2]), "r"(a[3]), "r"(b[0]), "r"(b[1]));
}

// ---------------- TF32 mma.sync GEMM: C = (A@W^T + b) * alpha ---------------
#define BMG 128
#define BNG 128
#define BKG 32
#define SSTR 36
#define GEMM_SMEM (2 * (BMG + BNG) * SSTR * 4)   // 73728 bytes

__device__ void gemm_core(const float* __restrict__ A, const float* __restrict__ W,
                          const float* __restrict__ bias, float* __restrict__ C,
                          int M, int N, int K, float alpha, float* sm) {
    float* As = sm;
    float* Bs = sm + 2 * BMG * SSTR;

    int tid = threadIdx.x;
    int warp = tid >> 5, lane = tid & 31;
    int warp_m = warp >> 2;
    int warp_n = warp & 3;
    int gr = lane >> 2, gc = lane & 3;

    int bm = blockIdx.y * BMG;
    int bn = blockIdx.x * BNG;

    int lrow = tid >> 3;
    int lc4  = (tid & 7) * 4;

    const float* Ap = A + (size_t)(bm + lrow) * K + lc4;
    const float* Wp = W + (size_t)(bn + lrow) * K + lc4;

    float c[4][4][4];
#pragma unroll
    for (int t = 0; t < 4; t++)
#pragma unroll
        for (int u = 0; u < 4; u++)
#pragma unroll
            for (int e = 0; e < 4; e++) c[t][u][e] = 0.f;

    float4 areg[4], breg[4];
    int nch = K / BKG;

#pragma unroll
    for (int it = 0; it < 4; it++) {
        areg[it] = *(const float4*)(Ap + (size_t)it * 32 * K);
        breg[it] = *(const float4*)(Wp + (size_t)it * 32 * K);
    }
#pragma unroll
    for (int it = 0; it < 4; it++) {
        float* da = As + (lrow + it * 32) * SSTR + lc4;
        float* db = Bs + (lrow + it * 32) * SSTR + lc4;
        ((uint32_t*)da)[0] = f2tf32(areg[it].x); ((uint32_t*)da)[1] = f2tf32(areg[it].y);
        ((uint32_t*)da)[2] = f2tf32(areg[it].z); ((uint32_t*)da)[3] = f2tf32(areg[it].w);
        ((uint32_t*)db)[0] = f2tf32(breg[it].x); ((uint32_t*)db)[1] = f2tf32(breg[it].y);
        ((uint32_t*)db)[2] = f2tf32(breg[it].z); ((uint32_t*)db)[3] = f2tf32(breg[it].w);
    }
    __syncthreads();

    for (int ch = 0; ch < nch; ch++) {
        int buf = ch & 1;
        if (ch + 1 < nch) {
            int k0n = (ch + 1) * BKG;
#pragma unroll
            for (int it = 0; it < 4; it++) {
                areg[it] = *(const float4*)(Ap + (size_t)it * 32 * K + k0n);
                breg[it] = *(const float4*)(Wp + (size_t)it * 32 * K + k0n);
            }
        }
        const uint32_t* as = (const uint32_t*)(As + buf * BMG * SSTR + warp_m * 64 * SSTR);
        const uint32_t* bs = (const uint32_t*)(Bs + buf * BNG * SSTR + warp_n * 32 * SSTR);
#pragma unroll
        for (int ks = 0; ks < 4; ks++) {
            int k0 = ks * 8;
            uint32_t af[4][4], bf[4][2];
#pragma unroll
            for (int t = 0; t < 4; t++) {
                int row = t * 16 + gr;
                af[t][0] = as[row * SSTR + k0 + gc];
                af[t][1] = as[(row + 8) * SSTR + k0 + gc];
                af[t][2] = as[row * SSTR + k0 + gc + 4];
                af[t][3] = as[(row + 8) * SSTR + k0 + gc + 4];
            }
#pragma unroll
            for (int u = 0; u < 4; u++) {
                int col = u * 8 + gr;
                bf[u][0] = bs[col * SSTR + k0 + gc];
                bf[u][1] = bs[col * SSTR + k0 + gc + 4];
            }
#pragma unroll
            for (int t = 0; t < 4; t++)
#pragma unroll
                for (int u = 0; u < 4; u++)
                    mma_tf32(c[t][u], af[t], bf[u]);
        }
        __syncthreads();
        if (ch + 1 < nch) {
            int nbuf = (ch + 1) & 1;
#pragma unroll
            for (int it = 0; it < 4; it++) {
                float* da = As + nbuf * BMG * SSTR + (lrow + it * 32) * SSTR + lc4;
                float* db = Bs + nbuf * BNG * SSTR + (lrow + it * 32) * SSTR + lc4;
                ((uint32_t*)da)[0] = f2tf32(areg[it].x); ((uint32_t*)da)[1] = f2tf32(areg[it].y);
                ((uint32_t*)da)[2] = f2tf32(areg[it].z); ((uint32_t*)da)[3] = f2tf32(areg[it].w);
                ((uint32_t*)db)[0] = f2tf32(breg[it].x); ((uint32_t*)db)[1] = f2tf32(breg[it].y);
                ((uint32_t*)db)[2] = f2tf32(breg[it].z); ((uint32_t*)db)[3] = f2tf32(breg[it].w);
            }
            __syncthreads();
        }
    }

#pragma unroll
    for (int t = 0; t < 4; t++) {
        int row = bm + warp_m * 64 + t * 16 + gr;
#pragma unroll
        for (int u = 0; u < 4; u++) {
            int col = bn + warp_n * 32 + u * 8 + 2 * gc;
            float2 bb = *(const float2*)(bias + col);
            float2 o0, o1;
            o0.x = (c[t][u][0] + bb.x) * alpha;
            o0.y = (c[t][u][1] + bb.y) * alpha;
            o1.x = (c[t][u][2] + bb.x) * alpha;
            o1.y = (c[t][u][3] + bb.y) * alpha;
            *(float2*)(C + (size_t)row * N + col) = o0;
            *(float2*)(C + (size_t)(row + 8) * N + col) = o1;
        }
    }
}

__global__ __launch_bounds__(256)
void qkv_gemm_kernel(const float* q_in, const float* k_in, const float* v_in,
                     const float* Wq, const float* Wk, const float* Wv,
                     const float* bq, const float* bk, const float* bv,
                     float* qo, float* ko, float* vo,
                     int M, int N, int K, float scaling,
                     const float* __restrict__ temp_ptr) {
    extern __shared__ float smg[];
    int z = blockIdx.z;
    const float* A; const float* W; const float* bias; float* C; float alpha;
    if (z == 0)      { A = q_in; W = Wq; bias = bq; C = qo; alpha = scaling * (*temp_ptr); }
    else if (z == 1) { A = k_in; W = Wk; bias = bk; C = ko; alpha = 1.0f; }
    else             { A = v_in; W = Wv; bias = bv; C = vo; alpha = 1.0f; }
    gemm_core(A, W, bias, C, M, N, K, alpha, smg);
}

__global__ __launch_bounds__(256)
void oproj_gemm_kernel(const float* __restrict__ A, const float* __restrict__ W,
                       const float* __restrict__ bias, float* __restrict__ C,
                       int M, int N, int K) {
    extern __shared__ float smg[];
    gemm_core(A, W, bias, C, M, N, K, 1.0f, smg);
}

// ---------------- mma.sync flash attention (double-buffered) ----------------
// 8 warps x m16 rows; 64-col tiles; QK^T and PV on tensor cores (tf32).
// V split hi+lo tf32 for accuracy. K/VH/VL double-buffered in smem with
// register prefetch of the next tile's global loads; ONE sync per tile.
#define AT_BM 128
#define AT_BN 64
#define KSTR 36                        // u32 stride, K/Vh/Vl tiles
#define PSTR 68                        // u32 stride, P staging
#define KVBLK (3 * 64 * KSTR)          // one buffer block (K,VH,VL) = 6912 u32
#define OFF_P  (2 * KVBLK)
#define OFF_GJ (OFF_P + 128 * PSTR)
#define ATT_SMEM ((OFF_GJ + 64) * 4)   // 90368 bytes

__global__ __launch_bounds__(256)
void sparse_attn_kernel(int T, int S, int E, const int* __restrict__ Wptr) {
    extern __shared__ float smf[];
    uint32_t* smu = (uint32_t*)smf;
    int* smgj = (int*)(smu + OFF_GJ);

    int b = blockIdx.z, h = blockIdx.y;
    int i0 = blockIdx.x * AT_BM;
    int tid = threadIdx.x;
    int w = tid >> 5, lane = tid & 31;
    int gr = lane >> 2, gc = lane & 3;
    int r0 = i0 + w * 16 + gr;
    int r1 = r0 + 8;

    const float* qb = g_q + (size_t)(b * T) * E + h * HD;
    const float* kbase = g_k + (size_t)b * S * E + h * HD;
    const float* vbase = g_v + (size_t)b * S * E + h * HD;

    // Q fragments (m16 k32, tf32)
    uint32_t qf[4][4];
#pragma unroll
    for (int kc = 0; kc < 4; kc++) {
        qf[kc][0] = f2tf32(qb[(size_t)r0 * E + kc * 8 + gc]);
        qf[kc][1] = f2tf32(qb[(size_t)r1 * E + kc * 8 + gc]);
        qf[kc][2] = f2tf32(qb[(size_t)r0 * E + kc * 8 + gc + 4]);
        qf[kc][3] = f2tf32(qb[(size_t)r1 * E + kc * 8 + gc + 4]);
    }

    int Wl = *Wptr;
    int ov = Wl / 4, step = Wl - ov;

    int klo0 = (r0 >= Wl) ? (r0 - Wl) / step + 1 : 0;
    int khi0 = r0 / step;
    int rlo0 = max(0, klo0 * step - ov);
    int rhi0 = min(S, khi0 * step + Wl + ov);
    int klo1 = (r1 >= Wl) ? (r1 - Wl) / step + 1 : 0;
    int khi1 = r1 / step;
    int rlo1 = max(0, klo1 * step - ov);
    int rhi1 = min(S, khi1 * step + Wl + ov);

    int cklo = (i0 >= Wl) ? (i0 - Wl) / step + 1 : 0;
    int ckhi = (i0 + AT_BM - 1) / step;
    int c_lo = max(0, cklo * step - ov);
    int c_hi = min(S, ckhi * step + Wl + ov);

    float m0 = -1e30f, m1 = -1e30f, l0 = 0.f, l1 = 0.f;
    float o[4][4];
#pragma unroll
    for (int dn = 0; dn < 4; dn++)
#pragma unroll
        for (int e = 0; e < 4; e++) o[dn][e] = 0.f;

    int lrow = tid >> 2;            // 0..63 : tile col (seq) loaded by this thread
    int lpart = (tid & 3) * 8;      // dim part

    int prow0 = OFF_P + (w * 16 + gr) * PSTR;
    int prow1 = prow0 + 8 * PSTR;

    // ---- global->register prefetch of one tile's slice ----
    auto ldg_tile = [&](int j0, float4* kv, float4* vv) {
        const float* kp = kbase + (size_t)(j0 + lrow) * E + lpart;
        const float* vp = vbase + (size_t)(j0 + lrow) * E + lpart;
        kv[0] = *(const float4*)(kp);
        kv[1] = *(const float4*)(kp + 4);
        vv[0] = *(const float4*)(vp);
        vv[1] = *(const float4*)(vp + 4);
    };
    // ---- register->smem (with tf32 cvt + V hi/lo split) ----
    auto sts_tile = [&](int base, const float4* kv, const float4* vv) {
#pragma unroll
        for (int c4 = 0; c4 < 2; c4++) {
            float4 kvv = kv[c4];
            uint4 kt;
            kt.x = f2tf32(kvv.x); kt.y = f2tf32(kvv.y);
            kt.z = f2tf32(kvv.z); kt.w = f2tf32(kvv.w);
            *(uint4*)&smu[base + lrow * KSTR + lpart + c4 * 4] = kt;
            float4 vvv = vv[c4];
            uint4 vh;
            vh.x = f2tf32(vvv.x); vh.y = f2tf32(vvv.y);
            vh.z = f2tf32(vvv.z); vh.w = f2tf32(vvv.w);
            uint4 vl;
            vl.x = f2tf32(vvv.x - __uint_as_float(vh.x));
            vl.y = f2tf32(vvv.y - __uint_as_float(vh.y));
            vl.z = f2tf32(vvv.z - __uint_as_float(vh.z));
            vl.w = f2tf32(vvv.w - __uint_as_float(vh.w));
            *(uint4*)&smu[base + 64 * KSTR + lrow * KSTR + lpart + c4 * 4] = vh;
            *(uint4*)&smu[base + 2 * 64 * KSTR + lrow * KSTR + lpart + c4 * 4] = vl;
        }
    };

    auto compute_tile = [&](int j0, int base, bool gather, int ng) {
        int offk  = base;
        int offvh = base + 64 * KSTR;
        int offvl = base + 2 * 64 * KSTR;
        // ---- QK^T: S fragments ----
        float c[8][4];
#pragma unroll
        for (int n = 0; n < 8; n++) {
            c[n][0] = 0.f; c[n][1] = 0.f; c[n][2] = 0.f; c[n][3] = 0.f;
#pragma unroll
            for (int kc = 0; kc < 4; kc++) {
                uint32_t bb[2];
                bb[0] = smu[offk + (n * 8 + gr) * KSTR + kc * 8 + gc];
                bb[1] = smu[offk + (n * 8 + gr) * KSTR + kc * 8 + gc + 4];
                mma_tf32(c[n], qf[kc], bb);
            }
        }
        // ---- masking ----
        bool fullmask = false;
        if (!gather) {
            bool f = (j0 >= rlo0) && (j0 + AT_BN <= rhi0) &&
                     (j0 >= rlo1) && (j0 + AT_BN <= rhi1);
            fullmask = __all_sync(0xffffffffu, f);
        }
        if (!fullmask) {
#pragma unroll
            for (int n = 0; n < 8; n++) {
                int e0 = n * 8 + 2 * gc, e1 = e0 + 1;
                bool v00, v01, v10, v11;
                if (!gather) {
                    int col0 = j0 + e0, col1 = j0 + e1;
                    v00 = (col0 >= rlo0) && (col0 < rhi0);
                    v01 = (col1 >= rlo0) && (col1 < rhi0);
                    v10 = (col0 >= rlo1) && (col0 < rhi1);
                    v11 = (col1 >= rlo1) && (col1 < rhi1);
                } else {
                    int gj0 = smgj[e0], gj1 = smgj[e1];
                    v00 = (e0 < ng) && ((gj0 < rlo0) || (gj0 >= rhi0));
                    v01 = (e1 < ng) && ((gj1 < rlo0) || (gj1 >= rhi0));
                    v10 = (e0 < ng) && ((gj0 < rlo1) || (gj0 >= rhi1));
                    v11 = (e1 < ng) && ((gj1 < rlo1) || (gj1 >= rhi1));
                }
                if (!v00) c[n][0] = -INFINITY;
                if (!v01) c[n][1] = -INFINITY;
                if (!v10) c[n][2] = -INFINITY;
                if (!v11) c[n][3] = -INFINITY;
            }
        }
        // ---- online softmax ----
        float cm0 = -INFINITY, cm1 = -INFINITY;
#pragma unroll
        for (int n = 0; n < 8; n++) {
            cm0 = fmaxf(cm0, fmaxf(c[n][0], c[n][1]));
            cm1 = fmaxf(cm1, fmaxf(c[n][2], c[n][3]));
        }
        cm0 = fmaxf(cm0, __shfl_xor_sync(0xffffffffu, cm0, 1));
        cm0 = fmaxf(cm0, __shfl_xor_sync(0xffffffffu, cm0, 2));
        cm1 = fmaxf(cm1, __shfl_xor_sync(0xffffffffu, cm1, 1));
        cm1 = fmaxf(cm1, __shfl_xor_sync(0xffffffffu, cm1, 2));
        float mn0 = fmaxf(m0, cm0), mn1 = fmaxf(m1, cm1);
        float sc0 = __expf(m0 - mn0), sc1 = __expf(m1 - mn1);
        m0 = mn0; m1 = mn1;
        l0 *= sc0; l1 *= sc1;
#pragma unroll
        for (int dn = 0; dn < 4; dn++) {
            o[dn][0] *= sc0; o[dn][1] *= sc0;
            o[dn][2] *= sc1; o[dn][3] *= sc1;
        }
        // ---- exp + stage P (tf32) ----
#pragma unroll
        for (int n = 0; n < 8; n++) {
            float p0 = __expf(c[n][0] - m0);
            float p1 = __expf(c[n][1] - m0);
            float p2 = __expf(c[n][2] - m1);
            float p3 = __expf(c[n][3] - m1);
            l0 += p0 + p1;
            l1 += p2 + p3;
            uint2 u0; u0.x = f2tf32(p0); u0.y = f2tf32(p1);
            *(uint2*)&smu[prow0 + n * 8 + 2 * gc] = u0;
            uint2 u1; u1.x = f2tf32(p2); u1.y = f2tf32(p3);
            *(uint2*)&smu[prow1 + n * 8 + 2 * gc] = u1;
        }
        __syncwarp();
        // ---- PV: O += P x (Vhi + Vlo) ----
#pragma unroll
        for (int k2 = 0; k2 < 8; k2++) {
            uint32_t a[4];
            a[0] = smu[prow0 + k2 * 8 + gc];
            a[1] = smu[prow1 + k2 * 8 + gc];
            a[2] = smu[prow0 + k2 * 8 + gc + 4];
            a[3] = smu[prow1 + k2 * 8 + gc + 4];
#pragma unroll
            for (int dn = 0; dn < 4; dn++) {
                uint32_t bh[2], bl[2];
                bh[0] = smu[offvh + (k2 * 8 + gc) * KSTR + dn * 8 + gr];
                bh[1] = smu[offvh + (k2 * 8 + gc + 4) * KSTR + dn * 8 + gr];
                mma_tf32(o[dn], a, bh);
                bl[0] = smu[offvl + (k2 * 8 + gc) * KSTR + dn * 8 + gr];
                bl[1] = smu[offvl + (k2 * 8 + gc + 4) * KSTR + dn * 8 + gr];
                mma_tf32(o[dn], a, bl);
            }
        }
    };

    // ---- main tiles: double-buffered with register prefetch ----
    int jstart = c_lo & ~(AT_BN - 1);
    int ntiles = (c_hi - jstart + AT_BN - 1) / AT_BN;

    float4 kvr[2], vvr[2];
    ldg_tile(jstart, kvr, vvr);
    sts_tile(0, kvr, vvr);
    __syncthreads();

    for (int idx = 0; idx < ntiles; idx++) {
        bool hasnext = (idx + 1 < ntiles);
        float4 kn[2], vn[2];
        if (hasnext) ldg_tile(jstart + (idx + 1) * AT_BN, kn, vn);   // LDGs overlap compute
        compute_tile(jstart + idx * AT_BN, (idx & 1) * KVBLK, false, 0);
        if (hasnext) sts_tile(((idx + 1) & 1) * KVBLK, kn, vn);
        __syncthreads();
    }

    // ---- gather tile: global columns (buffer 0; stale rows masked) ----
    int ng = g_gcount;
    if (ng > 0) {
        if (tid < 64) smgj[tid] = (tid < ng) ? g_gcols[tid] : 0x7fffffff;
        if (lrow < ng) {
            int j = g_gcols[lrow];
            float4 kg[2], vg[2];
            const float* kp = kbase + (size_t)j * E + lpart;
            const float* vp = vbase + (size_t)j * E + lpart;
            kg[0] = *(const float4*)(kp);
            kg[1] = *(const float4*)(kp + 4);
            vg[0] = *(const float4*)(vp);
            vg[1] = *(const float4*)(vp + 4);
            sts_tile(0, kg, vg);
        }
        __syncthreads();
        compute_tile(0, 0, true, ng);
    }

    // ---- finalize ----
    l0 += __shfl_xor_sync(0xffffffffu, l0, 1);
    l0 += __shfl_xor_sync(0xffffffffu, l0, 2);
    l1 += __shfl_xor_sync(0xffffffffu, l1, 1);
    l1 += __shfl_xor_sync(0xffffffffu, l1, 2);
    float inv0 = 1.0f / l0, inv1 = 1.0f / l1;

    float* o0p = g_ao + ((size_t)(b * T) + r0) * E + h * HD;
    float* o1p = g_ao + ((size_t)(b * T) + r1) * E + h * HD;
#pragma unroll
    for (int dn = 0; dn < 4; dn++) {
        float2 w0; w0.x = o[dn][0] * inv0; w0.y = o[dn][1] * inv0;
        float2 w1; w1.x = o[dn][2] * inv1; w1.y = o[dn][3] * inv1;
        *(float2*)(o0p + dn * 8 + 2 * gc) = w0;
        *(float2*)(o1p + dn * 8 + 2 * gc) = w1;
    }
}

// ---------------- launch -----------------------------------------------------
extern "C" void kernel_launch(void* const* d_in, const int* in_sizes, int n_in,
                              void* d_out, int out_size) {
    const float* query = (const float*)d_in[0];
    const float* key_  = (const float*)d_in[1];
    const float* value = (const float*)d_in[2];
    const float* Wq = (const float*)d_in[3];
    const float* bq = (const float*)d_in[4];
    const float* Wk = (const float*)d_in[5];
    const float* bk = (const float*)d_in[6];
    const float* Wv = (const float*)d_in[7];
    const float* bv = (const float*)d_in[8];
    const float* Wo = (const float*)d_in[9];
    const float* bo = (const float*)d_in[10];
    const float* temperature = (const float*)d_in[11];
    const int* wsize = (const int*)d_in[12];
    const int* gnum  = (const int*)d_in[13];
    float* out = (float*)d_out;

    int E = in_sizes[4];                 // 512
    int B = B_CONST;
    int T = in_sizes[0] / (B * E);       // 2048
    int S = in_sizes[1] / (B * E);       // 2048
    int M = B * T;                       // 4096
    int hd = E / H_NUM;

    float *qb, *kb, *vb, *aob;
    cudaGetSymbolAddress((void**)&qb,  g_q);
    cudaGetSymbolAddress((void**)&kb,  g_k);
    cudaGetSymbolAddress((void**)&vb,  g_v);
    cudaGetSymbolAddress((void**)&aob, g_ao);

    glist_kernel<<<1, 32>>>(S, gnum);

    cudaFuncSetAttribute(qkv_gemm_kernel,
                         cudaFuncAttributeMaxDynamicSharedMemorySize, GEMM_SMEM);
    cudaFuncSetAttribute(oproj_gemm_kernel,
                         cudaFuncAttributeMaxDynamicSharedMemorySize, GEMM_SMEM);

    float scaling = 1.0f / sqrtf((float)hd);
    dim3 qkv_grid(E / BNG, M / BMG, 3);          // (4, 32, 3)
    qkv_gemm_kernel<<<qkv_grid, 256, GEMM_SMEM>>>(
        query, key_, value, Wq, Wk, Wv, bq, bk, bv,
        qb, kb, vb, M, E, E, scaling, temperature);

    cudaFuncSetAttribute(sparse_attn_kernel,
                         cudaFuncAttributeMaxDynamicSharedMemorySize, ATT_SMEM);
    sparse_attn_kernel<<<dim3(T / AT_BM, H_NUM, B), 256, ATT_SMEM>>>(T, S, E, wsize);

    dim3 ogrid(E / BNG, M / BMG);                // (4, 32)
    oproj_gemm_kernel<<<ogrid, 256, GEMM_SMEM>>>(aob, Wo, bo, out, M, E, E);
}

// round 13
// speedup vs baseline: 1.0847x; 1.0847x over previous
#include <cuda_runtime.h>
#include <math.h>
#include <cstdint>

#define B_CONST 2
#define H_NUM   16
#define HD      32

// ---------------- device scratch ----------------
__device__ float g_q [2*2048*512];
__device__ float g_k [2*2048*512];
__device__ float g_v [2*2048*512];
__device__ float g_ao[2*2048*512];
__device__ int g_gcols[64];
__device__ int g_gcount;

// ---------------- global-token column list ----------------
__global__ void glist_kernel(int S, const int* __restrict__ Gptr) {
    if (threadIdx.x != 0 || blockIdx.x != 0) return;
    int G = *Gptr;
    int n = 0;
    if (G > 0) {
        int stride = S / (G + 1);
        if (G == 1) {
            g_gcols[n++] = stride;
        } else {
            double stp = (double)(S - 2 * stride) / (double)(G - 1);
            for (int t = 0; t < G && n < 64; t++) {
                long long gi = (t == G - 1)
                    ? (long long)(S - stride)
                    : (long long)((double)t * stp + (double)stride);
                bool dup = false;
                for (int u = 0; u < n; u++) if (g_gcols[u] == (int)gi) dup = true;
                if (!dup) g_gcols[n++] = (int)gi;
            }
        }
    }
    g_gcount = n;
}

// ---------------- shared helpers ----------------
__device__ __forceinline__ uint32_t f2tf32(float x) {
    uint32_t r;
    asm("cvt.rna.tf32.f32 %0, %1;" : "=r"(r) : "f"(x));
    return r;
}

__device__ __forceinline__ void mma_tf32(float* c, const uint32_t* a, const uint32_t* b) {
    asm volatile(
        "mma.sync.aligned.m16n8k8.row.col.f32.tf32.tf32.f32 "
        "{%0,%1,%2,%3}, {%4,%5,%6,%7}, {%8,%9}, {%0,%1,%2,%3};"
        : "+f"(c[0]), "+f"(c[1]), "+f"(c[2]), "+f"(c[3])
        : "r"(a[0]), "r"(a[1]), "r"(a[2]), "r"(a[3]), "r"(b[0]), "r"(b[1]));
}

// ---------------- TF32 mma.sync GEMM: C = (A@W^T + b) * alpha ---------------
// Double-buffered with ONE sync per K-chunk (store targets the buffer whose
// compute finished before the previous barrier).
#define BMG 128
#define BNG 128
#define BKG 32
#define SSTR 36
#define GEMM_SMEM (2 * (BMG + BNG) * SSTR * 4)   // 73728 bytes

__device__ void gemm_core(const float* __restrict__ A, const float* __restrict__ W,
                          const float* __restrict__ bias, float* __restrict__ C,
                          int M, int N, int K, float alpha, float* sm) {
    float* As = sm;
    float* Bs = sm + 2 * BMG * SSTR;

    int tid = threadIdx.x;
    int warp = tid >> 5, lane = tid & 31;
    int warp_m = warp >> 2;
    int warp_n = warp & 3;
    int gr = lane >> 2, gc = lane & 3;

    int bm = blockIdx.y * BMG;
    int bn = blockIdx.x * BNG;

    int lrow = tid >> 3;
    int lc4  = (tid & 7) * 4;

    const float* Ap = A + (size_t)(bm + lrow) * K + lc4;
    const float* Wp = W + (size_t)(bn + lrow) * K + lc4;

    float c[4][4][4];
#pragma unroll
    for (int t = 0; t < 4; t++)
#pragma unroll
        for (int u = 0; u < 4; u++)
#pragma unroll
            for (int e = 0; e < 4; e++) c[t][u][e] = 0.f;

    float4 areg[4], breg[4];
    int nch = K / BKG;

#pragma unroll
    for (int it = 0; it < 4; it++) {
        areg[it] = *(const float4*)(Ap + (size_t)it * 32 * K);
        breg[it] = *(const float4*)(Wp + (size_t)it * 32 * K);
    }
#pragma unroll
    for (int it = 0; it < 4; it++) {
        float* da = As + (lrow + it * 32) * SSTR + lc4;
        float* db = Bs + (lrow + it * 32) * SSTR + lc4;
        ((uint32_t*)da)[0] = f2tf32(areg[it].x); ((uint32_t*)da)[1] = f2tf32(areg[it].y);
        ((uint32_t*)da)[2] = f2tf32(areg[it].z); ((uint32_t*)da)[3] = f2tf32(areg[it].w);
        ((uint32_t*)db)[0] = f2tf32(breg[it].x); ((uint32_t*)db)[1] = f2tf32(breg[it].y);
        ((uint32_t*)db)[2] = f2tf32(breg[it].z); ((uint32_t*)db)[3] = f2tf32(breg[it].w);
    }
    __syncthreads();

    for (int ch = 0; ch < nch; ch++) {
        int buf = ch & 1;
        if (ch + 1 < nch) {
            int k0n = (ch + 1) * BKG;
#pragma unroll
            for (int it = 0; it < 4; it++) {
                areg[it] = *(const float4*)(Ap + (size_t)it * 32 * K + k0n);
                breg[it] = *(const float4*)(Wp + (size_t)it * 32 * K + k0n);
            }
        }
        const uint32_t* as = (const uint32_t*)(As + buf * BMG * SSTR + warp_m * 64 * SSTR);
        const uint32_t* bs = (const uint32_t*)(Bs + buf * BNG * SSTR + warp_n * 32 * SSTR);
#pragma unroll
        for (int ks = 0; ks < 4; ks++) {
            int k0 = ks * 8;
            uint32_t af[4][4], bf[4][2];
#pragma unroll
            for (int t = 0; t < 4; t++) {
                int row = t * 16 + gr;
                af[t][0] = as[row * SSTR + k0 + gc];
                af[t][1] = as[(row + 8) * SSTR + k0 + gc];
                af[t][2] = as[row * SSTR + k0 + gc + 4];
                af[t][3] = as[(row + 8) * SSTR + k0 + gc + 4];
            }
#pragma unroll
            for (int u = 0; u < 4; u++) {
                int col = u * 8 + gr;
                bf[u][0] = bs[col * SSTR + k0 + gc];
                bf[u][1] = bs[col * SSTR + k0 + gc + 4];
            }
#pragma unroll
            for (int t = 0; t < 4; t++)
#pragma unroll
                for (int u = 0; u < 4; u++)
                    mma_tf32(c[t][u], af[t], bf[u]);
        }
        // store next chunk into the OTHER buffer (its readers finished before
        // the previous barrier), then ONE sync.
        if (ch + 1 < nch) {
            int nbuf = (ch + 1) & 1;
#pragma unroll
            for (int it = 0; it < 4; it++) {
                float* da = As + nbuf * BMG * SSTR + (lrow + it * 32) * SSTR + lc4;
                float* db = Bs + nbuf * BNG * SSTR + (lrow + it * 32) * SSTR + lc4;
                ((uint32_t*)da)[0] = f2tf32(areg[it].x); ((uint32_t*)da)[1] = f2tf32(areg[it].y);
                ((uint32_t*)da)[2] = f2tf32(areg[it].z); ((uint32_t*)da)[3] = f2tf32(areg[it].w);
                ((uint32_t*)db)[0] = f2tf32(breg[it].x); ((uint32_t*)db)[1] = f2tf32(breg[it].y);
                ((uint32_t*)db)[2] = f2tf32(breg[it].z); ((uint32_t*)db)[3] = f2tf32(breg[it].w);
            }
            __syncthreads();
        }
    }

#pragma unroll
    for (int t = 0; t < 4; t++) {
        int row = bm + warp_m * 64 + t * 16 + gr;
#pragma unroll
        for (int u = 0; u < 4; u++) {
            int col = bn + warp_n * 32 + u * 8 + 2 * gc;
            float2 bb = *(const float2*)(bias + col);
            float2 o0, o1;
            o0.x = (c[t][u][0] + bb.x) * alpha;
            o0.y = (c[t][u][1] + bb.y) * alpha;
            o1.x = (c[t][u][2] + bb.x) * alpha;
            o1.y = (c[t][u][3] + bb.y) * alpha;
            *(float2*)(C + (size_t)row * N + col) = o0;
            *(float2*)(C + (size_t)(row + 8) * N + col) = o1;
        }
    }
}

// qkv: 384 CTAs (>=2 waves) -> 2 CTAs/SM is a real occupancy gain
__global__ __launch_bounds__(256, 2)
void qkv_gemm_kernel(const float* q_in, const float* k_in, const float* v_in,
                     const float* Wq, const float* Wk, const float* Wv,
                     const float* bq, const float* bk, const float* bv,
                     float* qo, float* ko, float* vo,
                     int M, int N, int K, float scaling,
                     const float* __restrict__ temp_ptr) {
    extern __shared__ float smg[];
    int z = blockIdx.z;
    const float* A; const float* W; const float* bias; float* C; float alpha;
    if (z == 0)      { A = q_in; W = Wq; bias = bq; C = qo; alpha = scaling * (*temp_ptr); }
    else if (z == 1) { A = k_in; W = Wk; bias = bk; C = ko; alpha = 1.0f; }
    else             { A = v_in; W = Wv; bias = bv; C = vo; alpha = 1.0f; }
    gemm_core(A, W, bias, C, M, N, K, alpha, smg);
}

// oproj: 128 CTAs (1 wave) -> clamping regs only hurts (R9); leave unclamped
__global__ __launch_bounds__(256)
void oproj_gemm_kernel(const float* __restrict__ A, const float* __restrict__ W,
                       const float* __restrict__ bias, float* __restrict__ C,
                       int M, int N, int K) {
    extern __shared__ float smg[];
    gemm_core(A, W, bias, C, M, N, K, 1.0f, smg);
}

// ---------------- mma.sync flash attention (R11 config — measured best) -----
// 8 warps x m16 rows; 64-col tiles; QK^T and PV on tensor cores (tf32).
// V split hi+lo tf32 for accuracy. Global cols = one synthetic gather tile.
#define AT_BM 128
#define AT_BN 64
#define KSTR 36                        // u32 stride, K/Vh/Vl tiles
#define PSTR 68                        // u32 stride, P staging
#define OFF_K  0
#define OFF_VH (64 * KSTR)
#define OFF_VL (2 * 64 * KSTR)
#define OFF_P  (3 * 64 * KSTR)
#define OFF_GJ (OFF_P + 128 * PSTR)
#define ATT_SMEM ((OFF_GJ + 64) * 4)   // 62720 bytes

__global__ __launch_bounds__(256)
void sparse_attn_kernel(int T, int S, int E, const int* __restrict__ Wptr) {
    extern __shared__ float smf[];
    uint32_t* smu = (uint32_t*)smf;
    int* smgj = (int*)(smu + OFF_GJ);

    int b = blockIdx.z, h = blockIdx.y;
    int i0 = blockIdx.x * AT_BM;
    int tid = threadIdx.x;
    int w = tid >> 5, lane = tid & 31;
    int gr = lane >> 2, gc = lane & 3;
    int r0 = i0 + w * 16 + gr;
    int r1 = r0 + 8;

    const float* qb = g_q + (size_t)(b * T) * E + h * HD;
    const float* kbase = g_k + (size_t)b * S * E + h * HD;
    const float* vbase = g_v + (size_t)b * S * E + h * HD;

    // Q fragments (m16 k32, tf32)
    uint32_t qf[4][4];
#pragma unroll
    for (int kc = 0; kc < 4; kc++) {
        qf[kc][0] = f2tf32(qb[(size_t)r0 * E + kc * 8 + gc]);
        qf[kc][1] = f2tf32(qb[(size_t)r1 * E + kc * 8 + gc]);
        qf[kc][2] = f2tf32(qb[(size_t)r0 * E + kc * 8 + gc + 4]);
        qf[kc][3] = f2tf32(qb[(size_t)r1 * E + kc * 8 + gc + 4]);
    }

    int Wl = *Wptr;
    int ov = Wl / 4, step = Wl - ov;

    int klo0 = (r0 >= Wl) ? (r0 - Wl) / step + 1 : 0;
    int khi0 = r0 / step;
    int rlo0 = max(0, klo0 * step - ov);
    int rhi0 = min(S, khi0 * step + Wl + ov);
    int klo1 = (r1 >= Wl) ? (r1 - Wl) / step + 1 : 0;
    int khi1 = r1 / step;
    int rlo1 = max(0, klo1 * step - ov);
    int rhi1 = min(S, khi1 * step + Wl + ov);

    int cklo = (i0 >= Wl) ? (i0 - Wl) / step + 1 : 0;
    int ckhi = (i0 + AT_BM - 1) / step;
    int c_lo = max(0, cklo * step - ov);
    int c_hi = min(S, ckhi * step + Wl + ov);

    float m0 = -1e30f, m1 = -1e30f, l0 = 0.f, l1 = 0.f;
    float o[4][4];
#pragma unroll
    for (int dn = 0; dn < 4; dn++)
#pragma unroll
        for (int e = 0; e < 4; e++) o[dn][e] = 0.f;

    int lrow = tid >> 2;            // 0..63 : tile col (seq) loaded by this thread
    int lpart = (tid & 3) * 8;      // dim part

    int prow0 = OFF_P + (w * 16 + gr) * PSTR;
    int prow1 = prow0 + 8 * PSTR;

    auto compute_tile = [&](int j0, bool gather, int ng) {
        // ---- QK^T: S fragments ----
        float c[8][4];
#pragma unroll
        for (int n = 0; n < 8; n++) {
            c[n][0] = 0.f; c[n][1] = 0.f; c[n][2] = 0.f; c[n][3] = 0.f;
#pragma unroll
            for (int kc = 0; kc < 4; kc++) {
                uint32_t bb[2];
                bb[0] = smu[OFF_K + (n * 8 + gr) * KSTR + kc * 8 + gc];
                bb[1] = smu[OFF_K + (n * 8 + gr) * KSTR + kc * 8 + gc + 4];
                mma_tf32(c[n], qf[kc], bb);
            }
        }
        // ---- masking ----
        bool fullmask = false;
        if (!gather) {
            bool f = (j0 >= rlo0) && (j0 + AT_BN <= rhi0) &&
                     (j0 >= rlo1) && (j0 + AT_BN <= rhi1);
            fullmask = __all_sync(0xffffffffu, f);
        }
        if (!fullmask) {
#pragma unroll
            for (int n = 0; n < 8; n++) {
                int e0 = n * 8 + 2 * gc, e1 = e0 + 1;
                bool v00, v01, v10, v11;
                if (!gather) {
                    int col0 = j0 + e0, col1 = j0 + e1;
                    v00 = (col0 >= rlo0) && (col0 < rhi0);
                    v01 = (col1 >= rlo0) && (col1 < rhi0);
                    v10 = (col0 >= rlo1) && (col0 < rhi1);
                    v11 = (col1 >= rlo1) && (col1 < rhi1);
                } else {
                    int gj0 = smgj[e0], gj1 = smgj[e1];
                    v00 = (e0 < ng) && ((gj0 < rlo0) || (gj0 >= rhi0));
                    v01 = (e1 < ng) && ((gj1 < rlo0) || (gj1 >= rhi0));
                    v10 = (e0 < ng) && ((gj0 < rlo1) || (gj0 >= rhi1));
                    v11 = (e1 < ng) && ((gj1 < rlo1) || (gj1 >= rhi1));
                }
                if (!v00) c[n][0] = -INFINITY;
                if (!v01) c[n][1] = -INFINITY;
                if (!v10) c[n][2] = -INFINITY;
                if (!v11) c[n][3] = -INFINITY;
            }
        }
        // ---- online softmax ----
        float cm0 = -INFINITY, cm1 = -INFINITY;
#pragma unroll
        for (int n = 0; n < 8; n++) {
            cm0 = fmaxf(cm0, fmaxf(c[n][0], c[n][1]));
            cm1 = fmaxf(cm1, fmaxf(c[n][2], c[n][3]));
        }
        cm0 = fmaxf(cm0, __shfl_xor_sync(0xffffffffu, cm0, 1));
        cm0 = fmaxf(cm0, __shfl_xor_sync(0xffffffffu, cm0, 2));
        cm1 = fmaxf(cm1, __shfl_xor_sync(0xffffffffu, cm1, 1));
        cm1 = fmaxf(cm1, __shfl_xor_sync(0xffffffffu, cm1, 2));
        float mn0 = fmaxf(m0, cm0), mn1 = fmaxf(m1, cm1);
        float sc0 = __expf(m0 - mn0), sc1 = __expf(m1 - mn1);
        m0 = mn0; m1 = mn1;
        l0 *= sc0; l1 *= sc1;
#pragma unroll
        for (int dn = 0; dn < 4; dn++) {
            o[dn][0] *= sc0; o[dn][1] *= sc0;
            o[dn][2] *= sc1; o[dn][3] *= sc1;
        }
        // ---- exp + stage P (tf32) ----
#pragma unroll
        for (int n = 0; n < 8; n++) {
            float p0 = __expf(c[n][0] - m0);
            float p1 = __expf(c[n][1] - m0);
            float p2 = __expf(c[n][2] - m1);
            float p3 = __expf(c[n][3] - m1);
            l0 += p0 + p1;
            l1 += p2 + p3;
            uint2 u0; u0.x = f2tf32(p0); u0.y = f2tf32(p1);
            *(uint2*)&smu[prow0 + n * 8 + 2 * gc] = u0;
            uint2 u1; u1.x = f2tf32(p2); u1.y = f2tf32(p3);
            *(uint2*)&smu[prow1 + n * 8 + 2 * gc] = u1;
        }
        __syncwarp();
        // ---- PV: O += P x (Vhi + Vlo) ----
#pragma unroll
        for (int k2 = 0; k2 < 8; k2++) {
            uint32_t a[4];
            a[0] = smu[prow0 + k2 * 8 + gc];
            a[1] = smu[prow1 + k2 * 8 + gc];
            a[2] = smu[prow0 + k2 * 8 + gc + 4];
            a[3] = smu[prow1 + k2 * 8 + gc + 4];
#pragma unroll
            for (int dn = 0; dn < 4; dn++) {
                uint32_t bh[2], bl[2];
                bh[0] = smu[OFF_VH + (k2 * 8 + gc) * KSTR + dn * 8 + gr];
                bh[1] = smu[OFF_VH + (k2 * 8 + gc + 4) * KSTR + dn * 8 + gr];
                mma_tf32(o[dn], a, bh);
                bl[0] = smu[OFF_VL + (k2 * 8 + gc) * KSTR + dn * 8 + gr];
                bl[1] = smu[OFF_VL + (k2 * 8 + gc + 4) * KSTR + dn * 8 + gr];
                mma_tf32(o[dn], a, bl);
            }
        }
    };

    // ---- main tiles over the CTA's contiguous range ----
    for (int j0 = (c_lo & ~(AT_BN - 1)); j0 < c_hi; j0 += AT_BN) {
        const float* kp = kbase + (size_t)(j0 + lrow) * E + lpart;
        const float* vp = vbase + (size_t)(j0 + lrow) * E + lpart;
#pragma unroll
        for (int c4 = 0; c4 < 8; c4 += 4) {
            float4 kv = *(const float4*)(kp + c4);
            uint4 kt;
            kt.x = f2tf32(kv.x); kt.y = f2tf32(kv.y);
            kt.z = f2tf32(kv.z); kt.w = f2tf32(kv.w);
            *(uint4*)&smu[OFF_K + lrow * KSTR + lpart + c4] = kt;
            float4 vv = *(const float4*)(vp + c4);
            uint4 vh;
            vh.x = f2tf32(vv.x); vh.y = f2tf32(vv.y);
            vh.z = f2tf32(vv.z); vh.w = f2tf32(vv.w);
            uint4 vl;
            vl.x = f2tf32(vv.x - __uint_as_float(vh.x));
            vl.y = f2tf32(vv.y - __uint_as_float(vh.y));
            vl.z = f2tf32(vv.z - __uint_as_float(vh.z));
            vl.w = f2tf32(vv.w - __uint_as_float(vh.w));
            *(uint4*)&smu[OFF_VH + lrow * KSTR + lpart + c4] = vh;
            *(uint4*)&smu[OFF_VL + lrow * KSTR + lpart + c4] = vl;
        }
        __syncthreads();
        compute_tile(j0, false, 0);
        __syncthreads();
    }

    // ---- gather tile: global columns ----
    int ng = g_gcount;
    if (ng > 0) {
        if (tid < 64) smgj[tid] = (tid < ng) ? g_gcols[tid] : 0x7fffffff;
        if (lrow < ng) {
            int j = g_gcols[lrow];
            const float* kp = kbase + (size_t)j * E + lpart;
            const float* vp = vbase + (size_t)j * E + lpart;
#pragma unroll
            for (int c4 = 0; c4 < 8; c4 += 4) {
                float4 kv = *(const float4*)(kp + c4);
                uint4 kt;
                kt.x = f2tf32(kv.x); kt.y = f2tf32(kv.y);
                kt.z = f2tf32(kv.z); kt.w = f2tf32(kv.w);
                *(uint4*)&smu[OFF_K + lrow * KSTR + lpart + c4] = kt;
                float4 vv = *(const float4*)(vp + c4);
                uint4 vh;
                vh.x = f2tf32(vv.x); vh.y = f2tf32(vv.y);
                vh.z = f2tf32(vv.z); vh.w = f2tf32(vv.w);
                uint4 vl;
                vl.x = f2tf32(vv.x - __uint_as_float(vh.x));
                vl.y = f2tf32(vv.y - __uint_as_float(vh.y));
                vl.z = f2tf32(vv.z - __uint_as_float(vh.z));
                vl.w = f2tf32(vv.w - __uint_as_float(vh.w));
                *(uint4*)&smu[OFF_VH + lrow * KSTR + lpart + c4] = vh;
                *(uint4*)&smu[OFF_VL + lrow * KSTR + lpart + c4] = vl;
            }
        }
        __syncthreads();
        compute_tile(0, true, ng);
    }

    // ---- finalize ----
    l0 += __shfl_xor_sync(0xffffffffu, l0, 1);
    l0 += __shfl_xor_sync(0xffffffffu, l0, 2);
    l1 += __shfl_xor_sync(0xffffffffu, l1, 1);
    l1 += __shfl_xor_sync(0xffffffffu, l1, 2);
    float inv0 = 1.0f / l0, inv1 = 1.0f / l1;

    float* o0p = g_ao + ((size_t)(b * T) + r0) * E + h * HD;
    float* o1p = g_ao + ((size_t)(b * T) + r1) * E + h * HD;
#pragma unroll
    for (int dn = 0; dn < 4; dn++) {
        float2 w0; w0.x = o[dn][0] * inv0; w0.y = o[dn][1] * inv0;
        float2 w1; w1.x = o[dn][2] * inv1; w1.y = o[dn][3] * inv1;
        *(float2*)(o0p + dn * 8 + 2 * gc) = w0;
        *(float2*)(o1p + dn * 8 + 2 * gc) = w1;
    }
}

// ---------------- launch -----------------------------------------------------
extern "C" void kernel_launch(void* const* d_in, const int* in_sizes, int n_in,
                              void* d_out, int out_size) {
    const float* query = (const float*)d_in[0];
    const float* key_  = (const float*)d_in[1];
    const float* value = (const float*)d_in[2];
    const float* Wq = (const float*)d_in[3];
    const float* bq = (const float*)d_in[4];
    const float* Wk = (const float*)d_in[5];
    const float* bk = (const float*)d_in[6];
    const float* Wv = (const float*)d_in[7];
    const float* bv = (const float*)d_in[8];
    const float* Wo = (const float*)d_in[9];
    const float* bo = (const float*)d_in[10];
    const float* temperature = (const float*)d_in[11];
    const int* wsize = (const int*)d_in[12];
    const int* gnum  = (const int*)d_in[13];
    float* out = (float*)d_out;

    int E = in_sizes[4];                 // 512
    int B = B_CONST;
    int T = in_sizes[0] / (B * E);       // 2048
    int S = in_sizes[1] / (B * E);       // 2048
    int M = B * T;                       // 4096
    int hd = E / H_NUM;

    float *qb, *kb, *vb, *aob;
    cudaGetSymbolAddress((void**)&qb,  g_q);
    cudaGetSymbolAddress((void**)&kb,  g_k);
    cudaGetSymbolAddress((void**)&vb,  g_v);
    cudaGetSymbolAddress((void**)&aob, g_ao);

    glist_kernel<<<1, 32>>>(S, gnum);

    cudaFuncSetAttribute(qkv_gemm_kernel,
                         cudaFuncAttributeMaxDynamicSharedMemorySize, GEMM_SMEM);
    cudaFuncSetAttribute(oproj_gemm_kernel,
                         cudaFuncAttributeMaxDynamicSharedMemorySize, GEMM_SMEM);

    float scaling = 1.0f / sqrtf((float)hd);
    dim3 qkv_grid(E / BNG, M / BMG, 3);          // (4, 32, 3)
    qkv_gemm_kernel<<<qkv_grid, 256, GEMM_SMEM>>>(
        query, key_, value, Wq, Wk, Wv, bq, bk, bv,
        qb, kb, vb, M, E, E, scaling, temperature);

    cudaFuncSetAttribute(sparse_attn_kernel,
                         cudaFuncAttributeMaxDynamicSharedMemorySize, ATT_SMEM);
    sparse_attn_kernel<<<dim3(T / AT_BM, H_NUM, B), 256, ATT_SMEM>>>(T, S, E, wsize);

    dim3 ogrid(E / BNG, M / BMG);                // (4, 32)
    oproj_gemm_kernel<<<ogrid, 256, GEMM_SMEM>>>(aob, Wo, bo, out, M, E, E);
}

// round 14
// speedup vs baseline: 1.1992x; 1.1056x over previous
#include <cuda_runtime.h>
#include <math.h>
#include <cstdint>

#define B_CONST 2
#define H_NUM   16
#define HD      32

// ---------------- device scratch ----------------
__device__ float g_q [2*2048*512];
__device__ float g_k [2*2048*512];
__device__ float g_v [2*2048*512];
__device__ float g_ao[2*2048*512];
__device__ int g_gcols[64];
__device__ int g_gcount;

// ---------------- global-token column list ----------------
__global__ void glist_kernel(int S, const int* __restrict__ Gptr) {
    if (threadIdx.x != 0 || blockIdx.x != 0) return;
    int G = *Gptr;
    int n = 0;
    if (G > 0) {
        int stride = S / (G + 1);
        if (G == 1) {
            g_gcols[n++] = stride;
        } else {
            double stp = (double)(S - 2 * stride) / (double)(G - 1);
            for (int t = 0; t < G && n < 64; t++) {
                long long gi = (t == G - 1)
                    ? (long long)(S - stride)
                    : (long long)((double)t * stp + (double)stride);
                bool dup = false;
                for (int u = 0; u < n; u++) if (g_gcols[u] == (int)gi) dup = true;
                if (!dup) g_gcols[n++] = (int)gi;
            }
        }
    }
    g_gcount = n;
}

// ---------------- shared helpers ----------------
__device__ __forceinline__ uint32_t f2tf32(float x) {
    uint32_t r;
    asm("cvt.rna.tf32.f32 %0, %1;" : "=r"(r) : "f"(x));
    return r;
}

__device__ __forceinline__ void mma_tf32(float* c, const uint32_t* a, const uint32_t* b) {
    asm volatile(
        "mma.sync.aligned.m16n8k8.row.col.f32.tf32.tf32.f32 "
        "{%0,%1,%2,%3}, {%4,%5,%6,%7}, {%8,%9}, {%0,%1,%2,%3};"
        : "+f"(c[0]), "+f"(c[1]), "+f"(c[2]), "+f"(c[3])
        : "r"(a[0]), "r"(a[1]), "r"(a[2]), "r"(a[3]), "r"(b[0]), "r"(b[1]));
}

// ---------------- TF32 mma.sync GEMM: C = (A@W^T + b) * alpha ---------------
// Double-buffered with ONE sync per K-chunk.
#define BMG 128
#define BNG 128
#define BKG 32
#define SSTR 36
#define GEMM_SMEM (2 * (BMG + BNG) * SSTR * 4)   // 73728 bytes

__device__ void gemm_core(const float* __restrict__ A, const float* __restrict__ W,
                          const float* __restrict__ bias, float* __restrict__ C,
                          int M, int N, int K, float alpha, float* sm) {
    float* As = sm;
    float* Bs = sm + 2 * BMG * SSTR;

    int tid = threadIdx.x;
    int warp = tid >> 5, lane = tid & 31;
    int warp_m = warp >> 2;
    int warp_n = warp & 3;
    int gr = lane >> 2, gc = lane & 3;

    int bm = blockIdx.y * BMG;
    int bn = blockIdx.x * BNG;

    int lrow = tid >> 3;
    int lc4  = (tid & 7) * 4;

    const float* Ap = A + (size_t)(bm + lrow) * K + lc4;
    const float* Wp = W + (size_t)(bn + lrow) * K + lc4;

    float c[4][4][4];
#pragma unroll
    for (int t = 0; t < 4; t++)
#pragma unroll
        for (int u = 0; u < 4; u++)
#pragma unroll
            for (int e = 0; e < 4; e++) c[t][u][e] = 0.f;

    float4 areg[4], breg[4];
    int nch = K / BKG;

#pragma unroll
    for (int it = 0; it < 4; it++) {
        areg[it] = *(const float4*)(Ap + (size_t)it * 32 * K);
        breg[it] = *(const float4*)(Wp + (size_t)it * 32 * K);
    }
#pragma unroll
    for (int it = 0; it < 4; it++) {
        float* da = As + (lrow + it * 32) * SSTR + lc4;
        float* db = Bs + (lrow + it * 32) * SSTR + lc4;
        ((uint32_t*)da)[0] = f2tf32(areg[it].x); ((uint32_t*)da)[1] = f2tf32(areg[it].y);
        ((uint32_t*)da)[2] = f2tf32(areg[it].z); ((uint32_t*)da)[3] = f2tf32(areg[it].w);
        ((uint32_t*)db)[0] = f2tf32(breg[it].x); ((uint32_t*)db)[1] = f2tf32(breg[it].y);
        ((uint32_t*)db)[2] = f2tf32(breg[it].z); ((uint32_t*)db)[3] = f2tf32(breg[it].w);
    }
    __syncthreads();

    for (int ch = 0; ch < nch; ch++) {
        int buf = ch & 1;
        if (ch + 1 < nch) {
            int k0n = (ch + 1) * BKG;
#pragma unroll
            for (int it = 0; it < 4; it++) {
                areg[it] = *(const float4*)(Ap + (size_t)it * 32 * K + k0n);
                breg[it] = *(const float4*)(Wp + (size_t)it * 32 * K + k0n);
            }
        }
        const uint32_t* as = (const uint32_t*)(As + buf * BMG * SSTR + warp_m * 64 * SSTR);
        const uint32_t* bs = (const uint32_t*)(Bs + buf * BNG * SSTR + warp_n * 32 * SSTR);
#pragma unroll
        for (int ks = 0; ks < 4; ks++) {
            int k0 = ks * 8;
            uint32_t af[4][4], bf[4][2];
#pragma unroll
            for (int t = 0; t < 4; t++) {
                int row = t * 16 + gr;
                af[t][0] = as[row * SSTR + k0 + gc];
                af[t][1] = as[(row + 8) * SSTR + k0 + gc];
                af[t][2] = as[row * SSTR + k0 + gc + 4];
                af[t][3] = as[(row + 8) * SSTR + k0 + gc + 4];
            }
#pragma unroll
            for (int u = 0; u < 4; u++) {
                int col = u * 8 + gr;
                bf[u][0] = bs[col * SSTR + k0 + gc];
                bf[u][1] = bs[col * SSTR + k0 + gc + 4];
            }
#pragma unroll
            for (int t = 0; t < 4; t++)
#pragma unroll
                for (int u = 0; u < 4; u++)
                    mma_tf32(c[t][u], af[t], bf[u]);
        }
        if (ch + 1 < nch) {
            int nbuf = (ch + 1) & 1;
#pragma unroll
            for (int it = 0; it < 4; it++) {
                float* da = As + nbuf * BMG * SSTR + (lrow + it * 32) * SSTR + lc4;
                float* db = Bs + nbuf * BMG * SSTR + (lrow + it * 32) * SSTR + lc4 + (BNG - BMG) * 0;
                db = Bs + nbuf * BNG * SSTR + (lrow + it * 32) * SSTR + lc4;
                ((uint32_t*)da)[0] = f2tf32(areg[it].x); ((uint32_t*)da)[1] = f2tf32(areg[it].y);
                ((uint32_t*)da)[2] = f2tf32(areg[it].z); ((uint32_t*)da)[3] = f2tf32(areg[it].w);
                ((uint32_t*)db)[0] = f2tf32(breg[it].x); ((uint32_t*)db)[1] = f2tf32(breg[it].y);
                ((uint32_t*)db)[2] = f2tf32(breg[it].z); ((uint32_t*)db)[3] = f2tf32(breg[it].w);
            }
            __syncthreads();
        }
    }

#pragma unroll
    for (int t = 0; t < 4; t++) {
        int row = bm + warp_m * 64 + t * 16 + gr;
#pragma unroll
        for (int u = 0; u < 4; u++) {
            int col = bn + warp_n * 32 + u * 8 + 2 * gc;
            float2 bb = *(const float2*)(bias + col);
            float2 o0, o1;
            o0.x = (c[t][u][0] + bb.x) * alpha;
            o0.y = (c[t][u][1] + bb.y) * alpha;
            o1.x = (c[t][u][2] + bb.x) * alpha;
            o1.y = (c[t][u][3] + bb.y) * alpha;
            *(float2*)(C + (size_t)row * N + col) = o0;
            *(float2*)(C + (size_t)(row + 8) * N + col) = o1;
        }
    }
}

// qkv: 384 CTAs (>=2 waves) -> 2 CTAs/SM is a real occupancy gain
__global__ __launch_bounds__(256, 2)
void qkv_gemm_kernel(const float* q_in, const float* k_in, const float* v_in,
                     const float* Wq, const float* Wk, const float* Wv,
                     const float* bq, const float* bk, const float* bv,
                     float* qo, float* ko, float* vo,
                     int M, int N, int K, float scaling,
                     const float* __restrict__ temp_ptr) {
    extern __shared__ float smg[];
    int z = blockIdx.z;
    const float* A; const float* W; const float* bias; float* C; float alpha;
    if (z == 0)      { A = q_in; W = Wq; bias = bq; C = qo; alpha = scaling * (*temp_ptr); }
    else if (z == 1) { A = k_in; W = Wk; bias = bk; C = ko; alpha = 1.0f; }
    else             { A = v_in; W = Wv; bias = bv; C = vo; alpha = 1.0f; }
    gemm_core(A, W, bias, C, M, N, K, alpha, smg);
}

// oproj: 128 CTAs (1 wave) -> clamping regs only hurts (R9); leave unclamped
__global__ __launch_bounds__(256)
void oproj_gemm_kernel(const float* __restrict__ A, const float* __restrict__ W,
                       const float* __restrict__ bias, float* __restrict__ C,
                       int M, int N, int K) {
    extern __shared__ float smg[];
    gemm_core(A, W, bias, C, M, N, K, 1.0f, smg);
}

// ---------------- mma.sync flash attention (no V-lo split) ------------------
// 8 warps x m16 rows; 64-col tiles; QK^T and PV on tensor cores (tf32).
// V stored as single tf32 (PV mmas halved vs R11/R13); smem 53.5KB -> 4 CTAs/SM.
#define AT_BM 128
#define AT_BN 64
#define KSTR 36                        // u32 stride, K/V tiles
#define PSTR 68                        // u32 stride, P staging
#define OFF_K  0
#define OFF_VH (64 * KSTR)
#define OFF_P  (2 * 64 * KSTR)
#define OFF_GJ (OFF_P + 128 * PSTR)
#define ATT_SMEM ((OFF_GJ + 64) * 4)   // 53504 bytes

__global__ __launch_bounds__(256)
void sparse_attn_kernel(int T, int S, int E, const int* __restrict__ Wptr) {
    extern __shared__ float smf[];
    uint32_t* smu = (uint32_t*)smf;
    int* smgj = (int*)(smu + OFF_GJ);

    int b = blockIdx.z, h = blockIdx.y;
    int i0 = blockIdx.x * AT_BM;
    int tid = threadIdx.x;
    int w = tid >> 5, lane = tid & 31;
    int gr = lane >> 2, gc = lane & 3;
    int r0 = i0 + w * 16 + gr;
    int r1 = r0 + 8;

    const float* qb = g_q + (size_t)(b * T) * E + h * HD;
    const float* kbase = g_k + (size_t)b * S * E + h * HD;
    const float* vbase = g_v + (size_t)b * S * E + h * HD;

    // Q fragments (m16 k32, tf32)
    uint32_t qf[4][4];
#pragma unroll
    for (int kc = 0; kc < 4; kc++) {
        qf[kc][0] = f2tf32(qb[(size_t)r0 * E + kc * 8 + gc]);
        qf[kc][1] = f2tf32(qb[(size_t)r1 * E + kc * 8 + gc]);
        qf[kc][2] = f2tf32(qb[(size_t)r0 * E + kc * 8 + gc + 4]);
        qf[kc][3] = f2tf32(qb[(size_t)r1 * E + kc * 8 + gc + 4]);
    }

    int Wl = *Wptr;
    int ov = Wl / 4, step = Wl - ov;

    int klo0 = (r0 >= Wl) ? (r0 - Wl) / step + 1 : 0;
    int khi0 = r0 / step;
    int rlo0 = max(0, klo0 * step - ov);
    int rhi0 = min(S, khi0 * step + Wl + ov);
    int klo1 = (r1 >= Wl) ? (r1 - Wl) / step + 1 : 0;
    int khi1 = r1 / step;
    int rlo1 = max(0, klo1 * step - ov);
    int rhi1 = min(S, khi1 * step + Wl + ov);

    int cklo = (i0 >= Wl) ? (i0 - Wl) / step + 1 : 0;
    int ckhi = (i0 + AT_BM - 1) / step;
    int c_lo = max(0, cklo * step - ov);
    int c_hi = min(S, ckhi * step + Wl + ov);

    float m0 = -1e30f, m1 = -1e30f, l0 = 0.f, l1 = 0.f;
    float o[4][4];
#pragma unroll
    for (int dn = 0; dn < 4; dn++)
#pragma unroll
        for (int e = 0; e < 4; e++) o[dn][e] = 0.f;

    int lrow = tid >> 2;            // 0..63 : tile col (seq) loaded by this thread
    int lpart = (tid & 3) * 8;      // dim part

    int prow0 = OFF_P + (w * 16 + gr) * PSTR;
    int prow1 = prow0 + 8 * PSTR;

    auto compute_tile = [&](int j0, bool gather, int ng) {
        // ---- QK^T: S fragments ----
        float c[8][4];
#pragma unroll
        for (int n = 0; n < 8; n++) {
            c[n][0] = 0.f; c[n][1] = 0.f; c[n][2] = 0.f; c[n][3] = 0.f;
#pragma unroll
            for (int kc = 0; kc < 4; kc++) {
                uint32_t bb[2];
                bb[0] = smu[OFF_K + (n * 8 + gr) * KSTR + kc * 8 + gc];
                bb[1] = smu[OFF_K + (n * 8 + gr) * KSTR + kc * 8 + gc + 4];
                mma_tf32(c[n], qf[kc], bb);
            }
        }
        // ---- masking ----
        bool fullmask = false;
        if (!gather) {
            bool f = (j0 >= rlo0) && (j0 + AT_BN <= rhi0) &&
                     (j0 >= rlo1) && (j0 + AT_BN <= rhi1);
            fullmask = __all_sync(0xffffffffu, f);
        }
        if (!fullmask) {
#pragma unroll
            for (int n = 0; n < 8; n++) {
                int e0 = n * 8 + 2 * gc, e1 = e0 + 1;
                bool v00, v01, v10, v11;
                if (!gather) {
                    int col0 = j0 + e0, col1 = j0 + e1;
                    v00 = (col0 >= rlo0) && (col0 < rhi0);
                    v01 = (col1 >= rlo0) && (col1 < rhi0);
                    v10 = (col0 >= rlo1) && (col0 < rhi1);
                    v11 = (col1 >= rlo1) && (col1 < rhi1);
                } else {
                    int gj0 = smgj[e0], gj1 = smgj[e1];
                    v00 = (e0 < ng) && ((gj0 < rlo0) || (gj0 >= rhi0));
                    v01 = (e1 < ng) && ((gj1 < rlo0) || (gj1 >= rhi0));
                    v10 = (e0 < ng) && ((gj0 < rlo1) || (gj0 >= rhi1));
                    v11 = (e1 < ng) && ((gj1 < rlo1) || (gj1 >= rhi1));
                }
                if (!v00) c[n][0] = -INFINITY;
                if (!v01) c[n][1] = -INFINITY;
                if (!v10) c[n][2] = -INFINITY;
                if (!v11) c[n][3] = -INFINITY;
            }
        }
        // ---- online softmax ----
        float cm0 = -INFINITY, cm1 = -INFINITY;
#pragma unroll
        for (int n = 0; n < 8; n++) {
            cm0 = fmaxf(cm0, fmaxf(c[n][0], c[n][1]));
            cm1 = fmaxf(cm1, fmaxf(c[n][2], c[n][3]));
        }
        cm0 = fmaxf(cm0, __shfl_xor_sync(0xffffffffu, cm0, 1));
        cm0 = fmaxf(cm0, __shfl_xor_sync(0xffffffffu, cm0, 2));
        cm1 = fmaxf(cm1, __shfl_xor_sync(0xffffffffu, cm1, 1));
        cm1 = fmaxf(cm1, __shfl_xor_sync(0xffffffffu, cm1, 2));
        float mn0 = fmaxf(m0, cm0), mn1 = fmaxf(m1, cm1);
        float sc0 = __expf(m0 - mn0), sc1 = __expf(m1 - mn1);
        m0 = mn0; m1 = mn1;
        l0 *= sc0; l1 *= sc1;
#pragma unroll
        for (int dn = 0; dn < 4; dn++) {
            o[dn][0] *= sc0; o[dn][1] *= sc0;
            o[dn][2] *= sc1; o[dn][3] *= sc1;
        }
        // ---- exp + stage P (tf32) ----
#pragma unroll
        for (int n = 0; n < 8; n++) {
            float p0 = __expf(c[n][0] - m0);
            float p1 = __expf(c[n][1] - m0);
            float p2 = __expf(c[n][2] - m1);
            float p3 = __expf(c[n][3] - m1);
            l0 += p0 + p1;
            l1 += p2 + p3;
            uint2 u0; u0.x = f2tf32(p0); u0.y = f2tf32(p1);
            *(uint2*)&smu[prow0 + n * 8 + 2 * gc] = u0;
            uint2 u1; u1.x = f2tf32(p2); u1.y = f2tf32(p3);
            *(uint2*)&smu[prow1 + n * 8 + 2 * gc] = u1;
        }
        __syncwarp();
        // ---- PV: O += P x V ----
#pragma unroll
        for (int k2 = 0; k2 < 8; k2++) {
            uint32_t a[4];
            a[0] = smu[prow0 + k2 * 8 + gc];
            a[1] = smu[prow1 + k2 * 8 + gc];
            a[2] = smu[prow0 + k2 * 8 + gc + 4];
            a[3] = smu[prow1 + k2 * 8 + gc + 4];
#pragma unroll
            for (int dn = 0; dn < 4; dn++) {
                uint32_t bh[2];
                bh[0] = smu[OFF_VH + (k2 * 8 + gc) * KSTR + dn * 8 + gr];
                bh[1] = smu[OFF_VH + (k2 * 8 + gc + 4) * KSTR + dn * 8 + gr];
                mma_tf32(o[dn], a, bh);
            }
        }
    };

    // ---- main tiles over the CTA's contiguous range ----
    for (int j0 = (c_lo & ~(AT_BN - 1)); j0 < c_hi; j0 += AT_BN) {
        const float* kp = kbase + (size_t)(j0 + lrow) * E + lpart;
        const float* vp = vbase + (size_t)(j0 + lrow) * E + lpart;
#pragma unroll
        for (int c4 = 0; c4 < 8; c4 += 4) {
            float4 kv = *(const float4*)(kp + c4);
            uint4 kt;
            kt.x = f2tf32(kv.x); kt.y = f2tf32(kv.y);
            kt.z = f2tf32(kv.z); kt.w = f2tf32(kv.w);
            *(uint4*)&smu[OFF_K + lrow * KSTR + lpart + c4] = kt;
            float4 vv = *(const float4*)(vp + c4);
            uint4 vh;
            vh.x = f2tf32(vv.x); vh.y = f2tf32(vv.y);
            vh.z = f2tf32(vv.z); vh.w = f2tf32(vv.w);
            *(uint4*)&smu[OFF_VH + lrow * KSTR + lpart + c4] = vh;
        }
        __syncthreads();
        compute_tile(j0, false, 0);
        __syncthreads();
    }

    // ---- gather tile: global columns ----
    int ng = g_gcount;
    if (ng > 0) {
        if (tid < 64) smgj[tid] = (tid < ng) ? g_gcols[tid] : 0x7fffffff;
        if (lrow < ng) {
            int j = g_gcols[lrow];
            const float* kp = kbase + (size_t)j * E + lpart;
            const float* vp = vbase + (size_t)j * E + lpart;
#pragma unroll
            for (int c4 = 0; c4 < 8; c4 += 4) {
                float4 kv = *(const float4*)(kp + c4);
                uint4 kt;
                kt.x = f2tf32(kv.x); kt.y = f2tf32(kv.y);
                kt.z = f2tf32(kv.z); kt.w = f2tf32(kv.w);
                *(uint4*)&smu[OFF_K + lrow * KSTR + lpart + c4] = kt;
                float4 vv = *(const float4*)(vp + c4);
                uint4 vh;
                vh.x = f2tf32(vv.x); vh.y = f2tf32(vv.y);
                vh.z = f2tf32(vv.z); vh.w = f2tf32(vv.w);
                *(uint4*)&smu[OFF_VH + lrow * KSTR + lpart + c4] = vh;
            }
        }
        __syncthreads();
        compute_tile(0, true, ng);
    }

    // ---- finalize ----
    l0 += __shfl_xor_sync(0xffffffffu, l0, 1);
    l0 += __shfl_xor_sync(0xffffffffu, l0, 2);
    l1 += __shfl_xor_sync(0xffffffffu, l1, 1);
    l1 += __shfl_xor_sync(0xffffffffu, l1, 2);
    float inv0 = 1.0f / l0, inv1 = 1.0f / l1;

    float* o0p = g_ao + ((size_t)(b * T) + r0) * E + h * HD;
    float* o1p = g_ao + ((size_t)(b * T) + r1) * E + h * HD;
#pragma unroll
    for (int dn = 0; dn < 4; dn++) {
        float2 w0; w0.x = o[dn][0] * inv0; w0.y = o[dn][1] * inv0;
        float2 w1; w1.x = o[dn][2] * inv1; w1.y = o[dn][3] * inv1;
        *(float2*)(o0p + dn * 8 + 2 * gc) = w0;
        *(float2*)(o1p + dn * 8 + 2 * gc) = w1;
    }
}

// ---------------- launch -----------------------------------------------------
extern "C" void kernel_launch(void* const* d_in, const int* in_sizes, int n_in,
                              void* d_out, int out_size) {
    const float* query = (const float*)d_in[0];
    const float* key_  = (const float*)d_in[1];
    const float* value = (const float*)d_in[2];
    const float* Wq = (const float*)d_in[3];
    const float* bq = (const float*)d_in[4];
    const float* Wk = (const float*)d_in[5];
    const float* bk = (const float*)d_in[6];
    const float* Wv = (const float*)d_in[7];
    const float* bv = (const float*)d_in[8];
    const float* Wo = (const float*)d_in[9];
    const float* bo = (const float*)d_in[10];
    const float* temperature = (const float*)d_in[11];
    const int* wsize = (const int*)d_in[12];
    const int* gnum  = (const int*)d_in[13];
    float* out = (float*)d_out;

    int E = in_sizes[4];                 // 512
    int B = B_CONST;
    int T = in_sizes[0] / (B * E);       // 2048
    int S = in_sizes[1] / (B * E);       // 2048
    int M = B * T;                       // 4096
    int hd = E / H_NUM;

    float *qb, *kb, *vb, *aob;
    cudaGetSymbolAddress((void**)&qb,  g_q);
    cudaGetSymbolAddress((void**)&kb,  g_k);
    cudaGetSymbolAddress((void**)&vb,  g_v);
    cudaGetSymbolAddress((void**)&aob, g_ao);

    glist_kernel<<<1, 32>>>(S, gnum);

    cudaFuncSetAttribute(qkv_gemm_kernel,
                         cudaFuncAttributeMaxDynamicSharedMemorySize, GEMM_SMEM);
    cudaFuncSetAttribute(oproj_gemm_kernel,
                         cudaFuncAttributeMaxDynamicSharedMemorySize, GEMM_SMEM);

    float scaling = 1.0f / sqrtf((float)hd);
    dim3 qkv_grid(E / BNG, M / BMG, 3);          // (4, 32, 3)
    qkv_gemm_kernel<<<qkv_grid, 256, GEMM_SMEM>>>(
        query, key_, value, Wq, Wk, Wv, bq, bk, bv,
        qb, kb, vb, M, E, E, scaling, temperature);

    cudaFuncSetAttribute(sparse_attn_kernel,
                         cudaFuncAttributeMaxDynamicSharedMemorySize, ATT_SMEM);
    sparse_attn_kernel<<<dim3(T / AT_BM, H_NUM, B), 256, ATT_SMEM>>>(T, S, E, wsize);

    dim3 ogrid(E / BNG, M / BMG);                // (4, 32)
    oproj_gemm_kernel<<<ogrid, 256, GEMM_SMEM>>>(aob, Wo, bo, out, M, E, E);
}